// round 9
// baseline (speedup 1.0000x reference)
#include <cuda_runtime.h>
#include <math.h>

#define B_  16
#define S_  8
#define H_  2048
#define NH_ 16
#define HD_ 128
#define ML_ 4104          // MAX_LEN
#define NSPLIT 8
#define ROWS_PER_WARP 65  // 64 warp-partitions * 65 >= 4104
#define PRE_ROWS 384      // rows [0,PRE) pre-copied during the qkv phase
#define FULLMASK 0xffffffffu

// Scratch (__device__ globals; no allocations allowed)
__device__ float g_q[B_ * NH_ * S_ * HD_];                 // q [bh][s][d], pre-scaled
__device__ float g_attn[B_ * S_ * H_];                     // attn out [b*s][h*128+d]
__device__ float g_part[B_ * NH_ * NSPLIT * S_ * HD_];     // partial O (unnormalized)
__device__ float g_l[B_ * NH_ * NSPLIT * S_];              // partial sum(exp)
__device__ int   g_ctr[B_ * NH_];                          // split-K fixup counters
__device__ float g_qkvp[4 * 128 * 6144];                   // qkv split-K partials
__device__ float g_projp[8 * 128 * 2048];                  // proj split-K partials

// ---------------------------------------------------------------------------
// GEMM1 + cache pre-copy (heterogeneous launch).
// z<4 : qkv partials [128,6144] = x @ in_w^T, split-K 4.
// z==4: 192 copy blocks stream rows [0,PRE_ROWS) of every (b,h) K and V from
//       the input caches to d_out (uses the DRAM bandwidth the FMA-bound GEMM
//       leaves idle). attn_kernel skips its stores for those rows.
// ---------------------------------------------------------------------------
__global__ __launch_bounds__(256)
void qkv_gemm_kernel(const float* __restrict__ x, const float* __restrict__ w,
                     const float* __restrict__ k_in, const float* __restrict__ v_in,
                     float* __restrict__ k_out, float* __restrict__ v_out)
{
    if (blockIdx.z == 4) {
        // ---- copy role ----
        const int bid = blockIdx.x + 96 * blockIdx.y;        // 0..191
        const int NF4 = 256 * PRE_ROWS * 32;                  // f4 per array
        const float4* kin4  = (const float4*)k_in;
        const float4* vin4  = (const float4*)v_in;
        float4* kout4 = (float4*)k_out;
        float4* vout4 = (float4*)v_out;
        for (int idx = bid * 256 + threadIdx.x; idx < 2 * NF4; idx += 192 * 256) {
            int arr = idx >= NF4;
            int i2  = arr ? idx - NF4 : idx;
            int bh  = i2 / (PRE_ROWS * 32);
            int r32 = i2 - bh * (PRE_ROWS * 32);
            size_t off = (size_t)bh * ML_ * 32 + r32;
            if (arr) __stcs(&vout4[off], __ldcs(&vin4[off]));
            else     __stcs(&kout4[off], __ldcs(&kin4[off]));
        }
        return;
    }

    // ---- gemm role ----
    __shared__ float As[32][64];
    __shared__ float Bs[32][64];
    const int t  = threadIdx.x;
    const int m0 = blockIdx.y * 64, n0 = blockIdx.x * 64;
    const int kbase = blockIdx.z * 512;
    const int tx = t & 15, ty = t >> 4;
    const int lr = t >> 2, lc = (t & 3) << 2;
    float acc[4][4] = {};
    const float* xp = x + (size_t)(m0 + lr) * 2048 + kbase + lc;
    const float* wp = w + (size_t)(n0 + lr) * 2048 + kbase + lc;
    for (int k0 = 0; k0 < 512; k0 += 32) {
        float4 a0 = *(const float4*)(xp + k0);
        float4 a1 = *(const float4*)(xp + k0 + 16);
        float4 b0 = *(const float4*)(wp + k0);
        float4 b1 = *(const float4*)(wp + k0 + 16);
        __syncthreads();
        As[lc+0][lr] = a0.x; As[lc+1][lr] = a0.y; As[lc+2][lr] = a0.z; As[lc+3][lr] = a0.w;
        As[lc+16][lr] = a1.x; As[lc+17][lr] = a1.y; As[lc+18][lr] = a1.z; As[lc+19][lr] = a1.w;
        Bs[lc+0][lr] = b0.x; Bs[lc+1][lr] = b0.y; Bs[lc+2][lr] = b0.z; Bs[lc+3][lr] = b0.w;
        Bs[lc+16][lr] = b1.x; Bs[lc+17][lr] = b1.y; Bs[lc+18][lr] = b1.z; Bs[lc+19][lr] = b1.w;
        __syncthreads();
        #pragma unroll
        for (int kk = 0; kk < 32; kk++) {
            float4 a4 = *(const float4*)&As[kk][ty << 2];
            float4 b4 = *(const float4*)&Bs[kk][tx << 2];
            float av[4] = {a4.x, a4.y, a4.z, a4.w};
            float bv[4] = {b4.x, b4.y, b4.z, b4.w};
            #pragma unroll
            for (int i = 0; i < 4; i++)
                #pragma unroll
                for (int j = 0; j < 4; j++)
                    acc[i][j] = fmaf(av[i], bv[j], acc[i][j]);
        }
    }
    float* dst = g_qkvp + (size_t)blockIdx.z * 128 * 6144;
    #pragma unroll
    for (int i = 0; i < 4; i++) {
        int m = m0 + (ty << 2) + i;
        #pragma unroll
        for (int j = 0; j < 4; j++) {
            int n = n0 + (tx << 2) + j;
            dst[(size_t)m * 6144 + n] = acc[i][j];
        }
    }
}

// Combine qkv partials + bias; q pre-scaled into g_q. Also resets g_ctr.
__global__ __launch_bounds__(256)
void qkv_combine_kernel(const float* __restrict__ bias, const int* __restrict__ cpp,
                        float* __restrict__ out_k, float* __restrict__ out_v)
{
    if (blockIdx.x == 0) g_ctr[threadIdx.x] = 0;    // reset fixup counters
    int idx = blockIdx.x * 256 + threadIdx.x;       // float4 idx, 196608 total
    int m = idx / 1536, n = (idx % 1536) << 2;
    float4 r = *(const float4*)&bias[n];
    #pragma unroll
    for (int z = 0; z < 4; z++) {
        float4 p = *(const float4*)&g_qkvp[(size_t)z * 128 * 6144 + (size_t)m * 6144 + n];
        r.x += p.x; r.y += p.y; r.z += p.z; r.w += p.w;
    }
    const int cp = *cpp;
    int bb = m >> 3, s = m & 7;
    if (n < 2048) {
        const float scale = 0.08838834764831845f;   // 1/sqrt(128)
        int h = n >> 7, d = n & 127;
        *(float4*)&g_q[(size_t)(((bb << 4) + h) * 8 + s) * 128 + d] =
            make_float4(r.x * scale, r.y * scale, r.z * scale, r.w * scale);
    } else if (n < 4096) {
        int c = n - 2048, h = c >> 7, d = c & 127;
        *(float4*)&out_k[((size_t)((bb << 4) + h) * ML_ + cp + s) * 128 + d] = r;
    } else {
        int c = n - 4096, h = c >> 7, d = c & 127;
        *(float4*)&out_v[((size_t)((bb << 4) + h) * ML_ + cp + s) * 128 + d] = r;
    }
}

// No-op spacer so attn_kernel lands in the ncu capture slot (4th launch).
__global__ void noop_kernel() {}

// ---------------------------------------------------------------------------
// Fused cache-copy + attention (DRAM-floor kernel; ~6.9TB/s effective).
// Stores skipped for pre-copied rows p < PRE_ROWS. Split-combine fused into
// the last-arriving block per (b,h) via atomic counter (split-K fixup).
// ---------------------------------------------------------------------------
__device__ __forceinline__
float4 ld_copy(const float4* __restrict__ in4, float4* __restrict__ out4,
               int p, int cp, int valid, int lane)
{
    size_t off = (size_t)p * 32 + lane;
    const float4* src = (p >= cp && p < valid) ? (const float4*)out4 : in4;
    float4 v = __ldcs(&src[off]);
    if (p >= PRE_ROWS) __stcs(&out4[off], v);       // pre-copied rows: skip
    return v;
}

__global__ __launch_bounds__(256, 2)
void attn_kernel(const float* __restrict__ k_in, const float* __restrict__ v_in,
                 const int* __restrict__ cpp,
                 float* __restrict__ k_out, float* __restrict__ v_out)
{
    const int t     = threadIdx.x;
    const int lane  = t & 31;
    const int w     = t >> 5;
    const int bh    = blockIdx.x;
    const int split = blockIdx.y;
    const int cp    = *cpp;
    const int valid = cp + S_;

    const float4* kin4  = (const float4*)k_in + (size_t)bh * ML_ * 32;
    const float4* vin4  = (const float4*)v_in + (size_t)bh * ML_ * 32;
    float4*       kout4 = (float4*)k_out + (size_t)bh * ML_ * 32;
    float4*       vout4 = (float4*)v_out + (size_t)bh * ML_ * 32;

    float4 q4[8];
    {
        const float4* qp = (const float4*)g_q + (size_t)bh * 256;
        #pragma unroll
        for (int q = 0; q < 8; q++) q4[q] = qp[q * 32 + lane];
    }

    float4 acc[8];
    #pragma unroll
    for (int q = 0; q < 8; q++) acc[q] = make_float4(0.f, 0.f, 0.f, 0.f);
    float l_dist = 0.f;                 // sum(exp) for query lane>>2

    const int wi = (split << 3) + w;                 // 0..63
    const int r0 = wi * ROWS_PER_WARP;
    const int r1 = min(r0 + ROWS_PER_WARP, ML_);
    const int lim = min(r1, valid);

    const bool hi16 = (lane & 16) != 0;
    const bool hi8  = (lane & 8) != 0;
    const bool hi4  = (lane & 4) != 0;

    for (int p0 = r0; p0 < r1; p0 += 4) {
        const int nr = min(4, r1 - p0);

        float4 kv[4];
        #pragma unroll
        for (int i = 0; i < 4; i++)
            kv[i] = (i < nr) ? ld_copy(kin4, kout4, p0 + i, cp, valid, lane)
                             : make_float4(0.f, 0.f, 0.f, 0.f);

        float pr[4];
        #pragma unroll
        for (int i = 0; i < 4; i++) {
            float s[8];
            #pragma unroll
            for (int q = 0; q < 8; q++)
                s[q] = fmaf(q4[q].x, kv[i].x, fmaf(q4[q].y, kv[i].y,
                       fmaf(q4[q].z, kv[i].z, q4[q].w * kv[i].w)));

            kv[i] = (i < nr) ? ld_copy(vin4, vout4, p0 + i, cp, valid, lane)
                             : make_float4(0.f, 0.f, 0.f, 0.f);

            #pragma unroll
            for (int j = 0; j < 4; j++) {
                float send = hi16 ? s[j] : s[j + 4];
                float recv = __shfl_xor_sync(FULLMASK, send, 16);
                s[j] = (hi16 ? s[j + 4] : s[j]) + recv;
            }
            #pragma unroll
            for (int j = 0; j < 2; j++) {
                float send = hi8 ? s[j] : s[j + 2];
                float recv = __shfl_xor_sync(FULLMASK, send, 8);
                s[j] = (hi8 ? s[j + 2] : s[j]) + recv;
            }
            {
                float send = hi4 ? s[0] : s[1];
                float recv = __shfl_xor_sync(FULLMASK, send, 4);
                s[0] = (hi4 ? s[1] : s[0]) + recv;
            }
            s[0] += __shfl_xor_sync(FULLMASK, s[0], 2);
            s[0] += __shfl_xor_sync(FULLMASK, s[0], 1);

            pr[i] = (p0 + i < lim) ? __expf(s[0]) : 0.f;
            l_dist += pr[i];
        }

        #pragma unroll
        for (int i = 0; i < 4; i++) {
            float4 v4 = kv[i];
            #pragma unroll
            for (int q = 0; q < 8; q++) {
                float pq = __shfl_sync(FULLMASK, pr[i], q << 2);
                acc[q].x = fmaf(pq, v4.x, acc[q].x);
                acc[q].y = fmaf(pq, v4.y, acc[q].y);
                acc[q].z = fmaf(pq, v4.z, acc[q].z);
                acc[q].w = fmaf(pq, v4.w, acc[q].w);
            }
        }
    }

    // ---- per-split reduction across the 8 warps ----
    __shared__ float4 red[8 * 8 * 32];   // [warp][query][lane] 32KB
    __shared__ float  lred[8][8];
    __shared__ int    is_last;
    #pragma unroll
    for (int q = 0; q < 8; q++)
        red[(w << 8) + (q << 5) + lane] = acc[q];
    if ((lane & 3) == 0) lred[w][lane >> 2] = l_dist;
    __syncthreads();

    const int qq = w;
    float4 o = make_float4(0.f, 0.f, 0.f, 0.f);
    #pragma unroll
    for (int ww = 0; ww < 8; ww++) {
        float4 p = red[(ww << 8) + (qq << 5) + lane];
        o.x += p.x; o.y += p.y; o.z += p.z; o.w += p.w;
    }
    ((float4*)g_part)[(((size_t)bh * NSPLIT + split) * 8 + qq) * 32 + lane] = o;
    if (lane == 0) {
        float L = 0.f;
        #pragma unroll
        for (int ww = 0; ww < 8; ww++) L += lred[ww][qq];
        g_l[((size_t)bh * NSPLIT + split) * 8 + qq] = L;
    }

    // ---- split-K fixup: last block for this bh combines all splits ----
    __threadfence();
    if (t == 0) is_last = (atomicAdd(&g_ctr[bh], 1) == NSPLIT - 1);
    __syncthreads();
    if (is_last) {
        const int q = t >> 5, ds = t & 31;
        float4 oc = make_float4(0.f, 0.f, 0.f, 0.f);
        float  L  = 0.f;
        #pragma unroll
        for (int s = 0; s < NSPLIT; s++) {
            float4 p = __ldcg(&((const float4*)g_part)[(((size_t)bh * NSPLIT + s) * 8 + q) * 32 + ds]);
            oc.x += p.x; oc.y += p.y; oc.z += p.z; oc.w += p.w;
            L += __ldcg(&g_l[((size_t)bh * NSPLIT + s) * 8 + q]);
        }
        float il = 1.f / L;
        int bb = bh >> 4, h = bh & 15;
        ((float4*)g_attn)[(size_t)(bb * 8 + q) * 512 + h * 32 + ds] =
            make_float4(oc.x * il, oc.y * il, oc.z * il, oc.w * il);
    }
}

// ---------------------------------------------------------------------------
// GEMM2: proj partials. [128,2048] = g_attn @ out_w^T, split-K 8 on z.
// ---------------------------------------------------------------------------
__global__ __launch_bounds__(256)
void proj_gemm_kernel(const float* __restrict__ w)
{
    __shared__ float As[32][64];
    __shared__ float Bs[32][64];
    const int t  = threadIdx.x;
    const int m0 = blockIdx.y * 64, n0 = blockIdx.x * 64;
    const int kbase = blockIdx.z * 256;
    const int tx = t & 15, ty = t >> 4;
    const int lr = t >> 2, lc = (t & 3) << 2;
    float acc[4][4] = {};
    const float* xp = g_attn + (size_t)(m0 + lr) * 2048 + kbase + lc;
    const float* wp = w + (size_t)(n0 + lr) * 2048 + kbase + lc;
    for (int k0 = 0; k0 < 256; k0 += 32) {
        float4 a0 = *(const float4*)(xp + k0);
        float4 a1 = *(const float4*)(xp + k0 + 16);
        float4 b0 = *(const float4*)(wp + k0);
        float4 b1 = *(const float4*)(wp + k0 + 16);
        __syncthreads();
        As[lc+0][lr] = a0.x; As[lc+1][lr] = a0.y; As[lc+2][lr] = a0.z; As[lc+3][lr] = a0.w;
        As[lc+16][lr] = a1.x; As[lc+17][lr] = a1.y; As[lc+18][lr] = a1.z; As[lc+19][lr] = a1.w;
        Bs[lc+0][lr] = b0.x; Bs[lc+1][lr] = b0.y; Bs[lc+2][lr] = b0.z; Bs[lc+3][lr] = b0.w;
        Bs[lc+16][lr] = b1.x; Bs[lc+17][lr] = b1.y; Bs[lc+18][lr] = b1.z; Bs[lc+19][lr] = b1.w;
        __syncthreads();
        #pragma unroll
        for (int kk = 0; kk < 32; kk++) {
            float4 a4 = *(const float4*)&As[kk][ty << 2];
            float4 b4 = *(const float4*)&Bs[kk][tx << 2];
            float av[4] = {a4.x, a4.y, a4.z, a4.w};
            float bv[4] = {b4.x, b4.y, b4.z, b4.w};
            #pragma unroll
            for (int i = 0; i < 4; i++)
                #pragma unroll
                for (int j = 0; j < 4; j++)
                    acc[i][j] = fmaf(av[i], bv[j], acc[i][j]);
        }
    }
    float* dst = g_projp + (size_t)blockIdx.z * 128 * 2048;
    #pragma unroll
    for (int i = 0; i < 4; i++) {
        int m = m0 + (ty << 2) + i;
        #pragma unroll
        for (int j = 0; j < 4; j++) {
            int n = n0 + (tx << 2) + j;
            dst[(size_t)m * 2048 + n] = acc[i][j];
        }
    }
}

__global__ __launch_bounds__(256)
void proj_combine_kernel(const float* __restrict__ bias, float* __restrict__ out)
{
    int idx = blockIdx.x * 256 + threadIdx.x;   // float4 idx, 65536 total
    int m = idx >> 9, n = (idx & 511) << 2;
    float4 r = *(const float4*)&bias[n];
    #pragma unroll
    for (int z = 0; z < 8; z++) {
        float4 p = *(const float4*)&g_projp[(size_t)z * 128 * 2048 + (size_t)m * 2048 + n];
        r.x += p.x; r.y += p.y; r.z += p.z; r.w += p.w;
    }
    *(float4*)&out[(size_t)m * 2048 + n] = r;
}

// ---------------------------------------------------------------------------
extern "C" void kernel_launch(void* const* d_in, const int* in_sizes, int n_in,
                              void* d_out, int out_size)
{
    const float* x     = (const float*)d_in[0];
    const float* kc    = (const float*)d_in[1];
    const float* vc    = (const float*)d_in[2];
    const float* in_w  = (const float*)d_in[3];
    const float* in_b  = (const float*)d_in[4];
    const float* out_w = (const float*)d_in[5];
    const float* out_b = (const float*)d_in[6];
    const int*   cpp   = (const int*)d_in[7];

    float* out   = (float*)d_out;                         // [16,8,2048]
    float* out_k = out + (size_t)B_ * S_ * H_;            // [16,16,4104,128]
    float* out_v = out_k + (size_t)B_ * NH_ * ML_ * HD_;  // [16,16,4104,128]

    // 1) qkv GEMM (z<4) + concurrent KV pre-copy of rows [0,PRE_ROWS) (z==4)
    qkv_gemm_kernel<<<dim3(96, 2, 5), 256>>>(x, in_w, kc, vc, out_k, out_v);
    // 2) combine partials + bias; scatter q / fresh kv rows; reset counters
    qkv_combine_kernel<<<768, 256>>>(in_b, cpp, out_k, out_v);
    noop_kernel<<<1, 32>>>();   // spacer: keeps attn in ncu's capture slot
    // 3) fused copy+attention with in-kernel split combine
    attn_kernel<<<dim3(256, NSPLIT), 256>>>(kc, vc, cpp, out_k, out_v);
    // 4) output projection
    proj_gemm_kernel<<<dim3(32, 2, 8), 256>>>(out_w);
    proj_combine_kernel<<<256, 256>>>(out_b, out);
}

// round 10
// speedup vs baseline: 1.1018x; 1.1018x over previous
#include <cuda_runtime.h>
#include <math.h>

#define B_  16
#define S_  8
#define H_  2048
#define NH_ 16
#define HD_ 128
#define ML_ 4104          // MAX_LEN
#define NSPLIT 8
#define ROWS_PER_WARP 65  // 64 warp-partitions * 65 >= 4104
#define QKV_Z 8           // qkv split-K factor
#define PROJ_Z 16         // proj split-K factor
#define FULLMASK 0xffffffffu

// Scratch (__device__ globals; no allocations allowed)
__device__ float g_q[B_ * NH_ * S_ * HD_];                 // q [bh][s][d], pre-scaled
__device__ float g_attn[B_ * S_ * H_];                     // attn out [b*s][h*128+d]
__device__ float g_part[B_ * NH_ * NSPLIT * S_ * HD_];     // partial O (unnormalized)
__device__ float g_l[B_ * NH_ * NSPLIT * S_];              // partial sum(exp)
__device__ float g_qkvp[QKV_Z * 128 * 6144];               // qkv split-K partials
__device__ float g_projp[PROJ_Z * 128 * 2048];             // proj split-K partials
__device__ int   g_qctr[192];                              // qkv tile fixup counters
__device__ int   g_pctr[64];                               // proj tile fixup counters

// ---------------------------------------------------------------------------
// GEMM1: qkv [128,6144] = x @ in_w^T, split-K 8, fused combine via fixup.
// Last z-block per (m,n) tile sums partials + bias and scatters q/k/v.
// Also resets proj fixup counters (runs before proj in every replay).
// ---------------------------------------------------------------------------
__global__ __launch_bounds__(256)
void qkv_gemm_kernel(const float* __restrict__ x, const float* __restrict__ w,
                     const float* __restrict__ bias, const int* __restrict__ cpp,
                     float* __restrict__ out_k, float* __restrict__ out_v)
{
    const int t = threadIdx.x;
    if (blockIdx.x == 0 && blockIdx.y == 0 && blockIdx.z == 0 && t < 64)
        g_pctr[t] = 0;                                  // reset proj counters

    __shared__ float As[32][64];
    __shared__ float Bs[32][64];
    const int m0 = blockIdx.y * 64, n0 = blockIdx.x * 64;
    const int kbase = blockIdx.z * (2048 / QKV_Z);
    const int tx = t & 15, ty = t >> 4;
    const int lr = t >> 2, lc = (t & 3) << 2;
    float acc[4][4] = {};
    const float* xp = x + (size_t)(m0 + lr) * 2048 + kbase + lc;
    const float* wp = w + (size_t)(n0 + lr) * 2048 + kbase + lc;
    for (int k0 = 0; k0 < 2048 / QKV_Z; k0 += 32) {
        float4 a0 = *(const float4*)(xp + k0);
        float4 a1 = *(const float4*)(xp + k0 + 16);
        float4 b0 = *(const float4*)(wp + k0);
        float4 b1 = *(const float4*)(wp + k0 + 16);
        __syncthreads();
        As[lc+0][lr] = a0.x; As[lc+1][lr] = a0.y; As[lc+2][lr] = a0.z; As[lc+3][lr] = a0.w;
        As[lc+16][lr] = a1.x; As[lc+17][lr] = a1.y; As[lc+18][lr] = a1.z; As[lc+19][lr] = a1.w;
        Bs[lc+0][lr] = b0.x; Bs[lc+1][lr] = b0.y; Bs[lc+2][lr] = b0.z; Bs[lc+3][lr] = b0.w;
        Bs[lc+16][lr] = b1.x; Bs[lc+17][lr] = b1.y; Bs[lc+18][lr] = b1.z; Bs[lc+19][lr] = b1.w;
        __syncthreads();
        #pragma unroll
        for (int kk = 0; kk < 32; kk++) {
            float4 a4 = *(const float4*)&As[kk][ty << 2];
            float4 b4 = *(const float4*)&Bs[kk][tx << 2];
            float av[4] = {a4.x, a4.y, a4.z, a4.w};
            float bv[4] = {b4.x, b4.y, b4.z, b4.w};
            #pragma unroll
            for (int i = 0; i < 4; i++)
                #pragma unroll
                for (int j = 0; j < 4; j++)
                    acc[i][j] = fmaf(av[i], bv[j], acc[i][j]);
        }
    }
    float* dst = g_qkvp + (size_t)blockIdx.z * 128 * 6144;
    #pragma unroll
    for (int i = 0; i < 4; i++) {
        int m = m0 + (ty << 2) + i;
        #pragma unroll
        for (int j = 0; j < 4; j++) {
            int n = n0 + (tx << 2) + j;
            dst[(size_t)m * 6144 + n] = acc[i][j];
        }
    }

    // ---- split-K fixup: last z-block for this tile combines + scatters ----
    __shared__ int is_last;
    __threadfence();
    if (t == 0)
        is_last = (atomicAdd(&g_qctr[blockIdx.y * 96 + blockIdx.x], 1) == QKV_Z - 1);
    __syncthreads();
    if (!is_last) return;

    const int cp = *cpp;
    // tile is 64 rows x 16 float4 cols = 1024 float4; 4 per thread
    #pragma unroll
    for (int e = 0; e < 4; e++) {
        int pos = (e << 8) + t;            // 0..1023
        int mi  = pos >> 4;                // row in tile
        int nj  = (pos & 15) << 2;         // float col in tile
        int m = m0 + mi, n = n0 + nj;
        float4 r = *(const float4*)&bias[n];
        #pragma unroll
        for (int z = 0; z < QKV_Z; z++) {
            float4 p = __ldcg((const float4*)&g_qkvp[(size_t)z * 128 * 6144 + (size_t)m * 6144 + n]);
            r.x += p.x; r.y += p.y; r.z += p.z; r.w += p.w;
        }
        int bb = m >> 3, s = m & 7;
        if (n < 2048) {
            const float scale = 0.08838834764831845f;   // 1/sqrt(128)
            int h = n >> 7, d = n & 127;
            *(float4*)&g_q[(size_t)(((bb << 4) + h) * 8 + s) * 128 + d] =
                make_float4(r.x * scale, r.y * scale, r.z * scale, r.w * scale);
        } else if (n < 4096) {
            int c = n - 2048, h = c >> 7, d = c & 127;
            *(float4*)&out_k[((size_t)((bb << 4) + h) * ML_ + cp + s) * 128 + d] = r;
        } else {
            int c = n - 4096, h = c >> 7, d = c & 127;
            *(float4*)&out_v[((size_t)((bb << 4) + h) * ML_ + cp + s) * 128 + d] = r;
        }
    }
}

// No-op spacers so attn_kernel stays launch #4 (ncu capture slot).
__global__ void noop_kernel() {}
__global__ void noop2_kernel() {}

// ---------------------------------------------------------------------------
// Fused cache-copy + attention — EXACT R8 hot loop (624us, near DRAM floor).
// ---------------------------------------------------------------------------
__device__ __forceinline__
float4 ld_copy(const float4* __restrict__ in4, float4* __restrict__ out4,
               int p, int cp, int valid, int lane)
{
    size_t off = (size_t)p * 32 + lane;
    const float4* src = (p >= cp && p < valid) ? (const float4*)out4 : in4;
    float4 v = __ldcs(&src[off]);
    __stcs(&out4[off], v);
    return v;
}

__global__ __launch_bounds__(256, 2)
void attn_kernel(const float* __restrict__ k_in, const float* __restrict__ v_in,
                 const int* __restrict__ cpp,
                 float* __restrict__ k_out, float* __restrict__ v_out)
{
    const int t     = threadIdx.x;
    const int lane  = t & 31;
    const int w     = t >> 5;
    const int bh    = blockIdx.x;
    const int split = blockIdx.y;
    const int cp    = *cpp;
    const int valid = cp + S_;

    const float4* kin4  = (const float4*)k_in + (size_t)bh * ML_ * 32;
    const float4* vin4  = (const float4*)v_in + (size_t)bh * ML_ * 32;
    float4*       kout4 = (float4*)k_out + (size_t)bh * ML_ * 32;
    float4*       vout4 = (float4*)v_out + (size_t)bh * ML_ * 32;

    float4 q4[8];
    {
        const float4* qp = (const float4*)g_q + (size_t)bh * 256;
        #pragma unroll
        for (int q = 0; q < 8; q++) q4[q] = qp[q * 32 + lane];
    }

    float4 acc[8];
    #pragma unroll
    for (int q = 0; q < 8; q++) acc[q] = make_float4(0.f, 0.f, 0.f, 0.f);
    float l_dist = 0.f;                 // sum(exp) for query lane>>2

    const int wi = (split << 3) + w;                 // 0..63
    const int r0 = wi * ROWS_PER_WARP;
    const int r1 = min(r0 + ROWS_PER_WARP, ML_);
    const int lim = min(r1, valid);

    const bool hi16 = (lane & 16) != 0;
    const bool hi8  = (lane & 8) != 0;
    const bool hi4  = (lane & 4) != 0;

    for (int p0 = r0; p0 < r1; p0 += 4) {
        const int nr = min(4, r1 - p0);

        float4 kv[4];
        #pragma unroll
        for (int i = 0; i < 4; i++)
            kv[i] = (i < nr) ? ld_copy(kin4, kout4, p0 + i, cp, valid, lane)
                             : make_float4(0.f, 0.f, 0.f, 0.f);

        float pr[4];
        #pragma unroll
        for (int i = 0; i < 4; i++) {
            float s[8];
            #pragma unroll
            for (int q = 0; q < 8; q++)
                s[q] = fmaf(q4[q].x, kv[i].x, fmaf(q4[q].y, kv[i].y,
                       fmaf(q4[q].z, kv[i].z, q4[q].w * kv[i].w)));

            kv[i] = (i < nr) ? ld_copy(vin4, vout4, p0 + i, cp, valid, lane)
                             : make_float4(0.f, 0.f, 0.f, 0.f);

            #pragma unroll
            for (int j = 0; j < 4; j++) {
                float send = hi16 ? s[j] : s[j + 4];
                float recv = __shfl_xor_sync(FULLMASK, send, 16);
                s[j] = (hi16 ? s[j + 4] : s[j]) + recv;
            }
            #pragma unroll
            for (int j = 0; j < 2; j++) {
                float send = hi8 ? s[j] : s[j + 2];
                float recv = __shfl_xor_sync(FULLMASK, send, 8);
                s[j] = (hi8 ? s[j + 2] : s[j]) + recv;
            }
            {
                float send = hi4 ? s[0] : s[1];
                float recv = __shfl_xor_sync(FULLMASK, send, 4);
                s[0] = (hi4 ? s[1] : s[0]) + recv;
            }
            s[0] += __shfl_xor_sync(FULLMASK, s[0], 2);
            s[0] += __shfl_xor_sync(FULLMASK, s[0], 1);

            pr[i] = (p0 + i < lim) ? __expf(s[0]) : 0.f;
            l_dist += pr[i];
        }

        #pragma unroll
        for (int i = 0; i < 4; i++) {
            float4 v4 = kv[i];
            #pragma unroll
            for (int q = 0; q < 8; q++) {
                float pq = __shfl_sync(FULLMASK, pr[i], q << 2);
                acc[q].x = fmaf(pq, v4.x, acc[q].x);
                acc[q].y = fmaf(pq, v4.y, acc[q].y);
                acc[q].z = fmaf(pq, v4.z, acc[q].z);
                acc[q].w = fmaf(pq, v4.w, acc[q].w);
            }
        }
    }

    __shared__ float4 red[8 * 8 * 32];   // [warp][query][lane] 32KB
    __shared__ float  lred[8][8];
    #pragma unroll
    for (int q = 0; q < 8; q++)
        red[(w << 8) + (q << 5) + lane] = acc[q];
    if ((lane & 3) == 0) lred[w][lane >> 2] = l_dist;
    __syncthreads();

    const int qq = w;
    float4 o = make_float4(0.f, 0.f, 0.f, 0.f);
    #pragma unroll
    for (int ww = 0; ww < 8; ww++) {
        float4 p = red[(ww << 8) + (qq << 5) + lane];
        o.x += p.x; o.y += p.y; o.z += p.z; o.w += p.w;
    }
    ((float4*)g_part)[(((size_t)bh * NSPLIT + split) * 8 + qq) * 32 + lane] = o;
    if (lane == 0) {
        float L = 0.f;
        #pragma unroll
        for (int ww = 0; ww < 8; ww++) L += lred[ww][qq];
        g_l[((size_t)bh * NSPLIT + split) * 8 + qq] = L;
    }
}

// Combine split partials -> g_attn. Also resets qkv fixup counters.
__global__ __launch_bounds__(256)
void attn_combine_kernel()
{
    const int bh = blockIdx.x, t = threadIdx.x;
    if (bh == 0 && t < 192) g_qctr[t] = 0;          // reset qkv counters
    const int q = t >> 5, ds = t & 31;
    float4 o = make_float4(0.f, 0.f, 0.f, 0.f);
    float L = 0.f;
    #pragma unroll
    for (int s = 0; s < NSPLIT; s++) {
        float4 p = ((const float4*)g_part)[(((size_t)bh * NSPLIT + s) * 8 + q) * 32 + ds];
        o.x += p.x; o.y += p.y; o.z += p.z; o.w += p.w;
        L += g_l[((size_t)bh * NSPLIT + s) * 8 + q];
    }
    float il = 1.f / L;
    int bb = bh >> 4, h = bh & 15;
    ((float4*)g_attn)[(size_t)(bb * 8 + q) * 512 + h * 32 + ds] =
        make_float4(o.x * il, o.y * il, o.z * il, o.w * il);
}

// ---------------------------------------------------------------------------
// GEMM2: out[128,2048] = g_attn @ out_w^T + out_b, split-K 16, fused fixup.
// ---------------------------------------------------------------------------
__global__ __launch_bounds__(256)
void proj_gemm_kernel(const float* __restrict__ w, const float* __restrict__ bias,
                      float* __restrict__ out)
{
    __shared__ float As[32][64];
    __shared__ float Bs[32][64];
    const int t  = threadIdx.x;
    const int m0 = blockIdx.y * 64, n0 = blockIdx.x * 64;
    const int kbase = blockIdx.z * (2048 / PROJ_Z);
    const int tx = t & 15, ty = t >> 4;
    const int lr = t >> 2, lc = (t & 3) << 2;
    float acc[4][4] = {};
    const float* xp = g_attn + (size_t)(m0 + lr) * 2048 + kbase + lc;
    const float* wp = w + (size_t)(n0 + lr) * 2048 + kbase + lc;
    for (int k0 = 0; k0 < 2048 / PROJ_Z; k0 += 32) {
        float4 a0 = *(const float4*)(xp + k0);
        float4 a1 = *(const float4*)(xp + k0 + 16);
        float4 b0 = *(const float4*)(wp + k0);
        float4 b1 = *(const float4*)(wp + k0 + 16);
        __syncthreads();
        As[lc+0][lr] = a0.x; As[lc+1][lr] = a0.y; As[lc+2][lr] = a0.z; As[lc+3][lr] = a0.w;
        As[lc+16][lr] = a1.x; As[lc+17][lr] = a1.y; As[lc+18][lr] = a1.z; As[lc+19][lr] = a1.w;
        Bs[lc+0][lr] = b0.x; Bs[lc+1][lr] = b0.y; Bs[lc+2][lr] = b0.z; Bs[lc+3][lr] = b0.w;
        Bs[lc+16][lr] = b1.x; Bs[lc+17][lr] = b1.y; Bs[lc+18][lr] = b1.z; Bs[lc+19][lr] = b1.w;
        __syncthreads();
        #pragma unroll
        for (int kk = 0; kk < 32; kk++) {
            float4 a4 = *(const float4*)&As[kk][ty << 2];
            float4 b4 = *(const float4*)&Bs[kk][tx << 2];
            float av[4] = {a4.x, a4.y, a4.z, a4.w};
            float bv[4] = {b4.x, b4.y, b4.z, b4.w};
            #pragma unroll
            for (int i = 0; i < 4; i++)
                #pragma unroll
                for (int j = 0; j < 4; j++)
                    acc[i][j] = fmaf(av[i], bv[j], acc[i][j]);
        }
    }
    float* dst = g_projp + (size_t)blockIdx.z * 128 * 2048;
    #pragma unroll
    for (int i = 0; i < 4; i++) {
        int m = m0 + (ty << 2) + i;
        #pragma unroll
        for (int j = 0; j < 4; j++) {
            int n = n0 + (tx << 2) + j;
            dst[(size_t)m * 2048 + n] = acc[i][j];
        }
    }

    // ---- split-K fixup: last z-block per tile sums + writes final out ----
    __shared__ int is_last;
    __threadfence();
    if (t == 0)
        is_last = (atomicAdd(&g_pctr[blockIdx.y * 32 + blockIdx.x], 1) == PROJ_Z - 1);
    __syncthreads();
    if (!is_last) return;

    #pragma unroll
    for (int e = 0; e < 4; e++) {
        int pos = (e << 8) + t;            // 0..1023
        int mi  = pos >> 4;
        int nj  = (pos & 15) << 2;
        int m = m0 + mi, n = n0 + nj;
        float4 r = *(const float4*)&bias[n];
        #pragma unroll
        for (int z = 0; z < PROJ_Z; z++) {
            float4 p = __ldcg((const float4*)&g_projp[(size_t)z * 128 * 2048 + (size_t)m * 2048 + n]);
            r.x += p.x; r.y += p.y; r.z += p.z; r.w += p.w;
        }
        *(float4*)&out[(size_t)m * 2048 + n] = r;
    }
}

// ---------------------------------------------------------------------------
extern "C" void kernel_launch(void* const* d_in, const int* in_sizes, int n_in,
                              void* d_out, int out_size)
{
    const float* x     = (const float*)d_in[0];
    const float* kc    = (const float*)d_in[1];
    const float* vc    = (const float*)d_in[2];
    const float* in_w  = (const float*)d_in[3];
    const float* in_b  = (const float*)d_in[4];
    const float* out_w = (const float*)d_in[5];
    const float* out_b = (const float*)d_in[6];
    const int*   cpp   = (const int*)d_in[7];

    float* out   = (float*)d_out;                         // [16,8,2048]
    float* out_k = out + (size_t)B_ * S_ * H_;            // [16,16,4104,128]
    float* out_v = out_k + (size_t)B_ * NH_ * ML_ * HD_;  // [16,16,4104,128]

    // 1) qkv GEMM with fused combine (fixup); also resets proj counters
    qkv_gemm_kernel<<<dim3(96, 2, QKV_Z), 256>>>(x, in_w, in_b, cpp, out_k, out_v);
    noop_kernel<<<1, 32>>>();    // spacers keep attn at launch #4 (ncu slot)
    noop2_kernel<<<1, 32>>>();
    // 2) fused copy+attention (R8 hot loop, untouched)
    attn_kernel<<<dim3(256, NSPLIT), 256>>>(kc, vc, cpp, out_k, out_v);
    // 3) split combine; resets qkv counters
    attn_combine_kernel<<<256, 256>>>();
    // 4) output projection with fused combine (fixup)
    proj_gemm_kernel<<<dim3(32, 2, PROJ_Z), 256>>>(out_w, out_b, out);
}